// round 7
// baseline (speedup 1.0000x reference)
#include <cuda_runtime.h>
#include <cstdint>

struct State { double acc; unsigned long long count; };
__device__ State g_state;

static constexpr int BLOCKS  = 592;    // 4 blocks/SM on 148 SMs, truly persistent
static constexpr int THREADS = 256;    // 8 warps/block
static constexpr int WARPS_TOTAL = BLOCKS * (THREADS / 32);

// Persistent warps, pipelined WITHOUT a snapshot buffer:
//   per row: (1) consume v[8] into 4 independent FMA accumulators (+ in-pass
//   label-component extraction), (2) issue next row's 8 loads into v,
//   (3) run the serial tail (shuffle reduce + sqrt + owner shuffle) behind
//   the in-flight loads. Live data = 8 float4s -> ~56 regs -> 4 blocks/SM.
__global__ __launch_bounds__(THREADS, 4)
void cosine_loss_kernel(const float* __restrict__ logits,
                        const int* __restrict__ labels,
                        int N, int C, float* __restrict__ out, double inv_n) {
    const int lane  = threadIdx.x & 31;
    const int warp_in_block = threadIdx.x >> 5;
    const int gwarp = blockIdx.x * (THREADS >> 5) + warp_in_block;

    double local = 0.0;

    int row = gwarp;
    float4 v[8];
    int lab = 0;

    // Prologue: loads for the first row.
    if (row < N) {
        const float4* __restrict__ row4 =
            reinterpret_cast<const float4*>(logits + (size_t)row * (size_t)C);
        lab = __ldg(labels + row);
        #pragma unroll
        for (int k = 0; k < 7; k++)
            v[k] = __ldcs(row4 + lane + 32 * k);
        v[7] = make_float4(0.f, 0.f, 0.f, 0.f);
        if (lane < 26)
            v[7] = __ldcs(row4 + lane + 224);
    }

    while (row < N) {
        const int labc = lab;
        const int j4   = labc >> 2;          // float4 index in row [0,250)
        const int comp = labc & 3;
        const int lane_owner = j4 & 31;

        // (1) Consume v: 4 independent accumulator chains + label extraction.
        float s0 = 0.f, s1 = 0.f, s2 = 0.f, s3 = 0.f;
        float dot_l = 0.0f;
        #pragma unroll
        for (int k = 0; k < 8; k++) {
            if (j4 == lane + 32 * k) {
                dot_l = (comp == 0) ? v[k].x :
                        (comp == 1) ? v[k].y :
                        (comp == 2) ? v[k].z : v[k].w;
            }
            s0 = fmaf(v[k].x, v[k].x, s0);
            s1 = fmaf(v[k].y, v[k].y, s1);
            s2 = fmaf(v[k].z, v[k].z, s2);
            s3 = fmaf(v[k].w, v[k].w, s3);
        }

        // (2) Issue next row's loads (v is dead now).
        const int next = row + WARPS_TOTAL;
        if (next < N) {
            const float4* __restrict__ row4 =
                reinterpret_cast<const float4*>(logits + (size_t)next * (size_t)C);
            lab = __ldg(labels + next);
            #pragma unroll
            for (int k = 0; k < 7; k++)
                v[k] = __ldcs(row4 + lane + 32 * k);
            v[7] = make_float4(0.f, 0.f, 0.f, 0.f);
            if (lane < 26)
                v[7] = __ldcs(row4 + lane + 224);
        }

        // (3) Serial tail, hidden behind the in-flight loads.
        float s = (s0 + s1) + (s2 + s3);
        #pragma unroll
        for (int o = 16; o > 0; o >>= 1)
            s += __shfl_xor_sync(0xFFFFFFFFu, s, o);
        const float dot = __shfl_sync(0xFFFFFFFFu, dot_l, lane_owner);

        if (lane == 0) {
            const float cosv = dot / fmaxf(sqrtf(s), 1e-8f);
            local += 1.0 - (double)cosv;
        }

        row = next;
    }

    // Block reduction, once per block.
    __shared__ double sh[THREADS >> 5];
    if (lane == 0) sh[warp_in_block] = local;
    __syncthreads();

    if (threadIdx.x == 0) {
        double t = 0.0;
        #pragma unroll
        for (int i = 0; i < (THREADS >> 5); i++) t += sh[i];
        atomicAdd(&g_state.acc, t);

        __threadfence();
        unsigned long long ticket = atomicAdd(&g_state.count, 1ULL);
        if (ticket == (unsigned long long)gridDim.x - 1ULL) {
            double acc = *(volatile double*)&g_state.acc;
            *out = (float)(acc * inv_n);
        }
    }
}

extern "C" void kernel_launch(void* const* d_in, const int* in_sizes, int n_in,
                              void* d_out, int out_size) {
    const float* logits = (const float*)d_in[0];
    const int*   labels = (const int*)d_in[1];
    float* out = (float*)d_out;

    const int N = in_sizes[1];          // rows == labels
    const int C = in_sizes[0] / N;      // 1000

    void* state_ptr = nullptr;
    cudaGetSymbolAddress(&state_ptr, g_state);
    cudaMemsetAsync(state_ptr, 0, sizeof(State), 0);

    cosine_loss_kernel<<<BLOCKS, THREADS>>>(logits, labels, N, C, out,
                                            1.0 / (double)N);
}

// round 8
// speedup vs baseline: 1.5568x; 1.5568x over previous
#include <cuda_runtime.h>
#include <cstdint>

struct State { double acc; unsigned long long count; };
__device__ State g_state;

static constexpr int BLOCKS  = 296;    // 2 blocks/SM on 148 SMs (regs ~120-128)
static constexpr int THREADS = 256;    // 8 warps/block
static constexpr int WARPS_TOTAL = BLOCKS * (THREADS / 32);

// 3-buffer rotation, prefetch distance 2: a row's 8 float4 loads are issued
// two consume-steps (~2 iteration bodies ~ DRAM latency) before they're read.
struct RowBuf { float4 v[8]; int lab; };

__device__ __forceinline__ void load_row(RowBuf& b,
                                         const float* __restrict__ logits,
                                         const int* __restrict__ labels,
                                         int row, int C, int lane) {
    const float4* __restrict__ row4 =
        reinterpret_cast<const float4*>(logits + (size_t)row * (size_t)C);
    b.lab = __ldg(labels + row);
    #pragma unroll
    for (int k = 0; k < 7; k++)
        b.v[k] = __ldcs(row4 + lane + 32 * k);
    b.v[7] = make_float4(0.f, 0.f, 0.f, 0.f);
    if (lane < 26)
        b.v[7] = __ldcs(row4 + lane + 224);
}

__device__ __forceinline__ void consume_row(const RowBuf& b, int lane,
                                            double& local) {
    const int j4   = b.lab >> 2;
    const int comp = b.lab & 3;
    const int lane_owner = j4 & 31;

    float s0 = 0.f, s1 = 0.f, s2 = 0.f, s3 = 0.f;
    float dot_l = 0.0f;
    #pragma unroll
    for (int k = 0; k < 8; k++) {
        if (j4 == lane + 32 * k) {
            dot_l = (comp == 0) ? b.v[k].x :
                    (comp == 1) ? b.v[k].y :
                    (comp == 2) ? b.v[k].z : b.v[k].w;
        }
        s0 = fmaf(b.v[k].x, b.v[k].x, s0);
        s1 = fmaf(b.v[k].y, b.v[k].y, s1);
        s2 = fmaf(b.v[k].z, b.v[k].z, s2);
        s3 = fmaf(b.v[k].w, b.v[k].w, s3);
    }
    float s = (s0 + s1) + (s2 + s3);
    #pragma unroll
    for (int o = 16; o > 0; o >>= 1)
        s += __shfl_xor_sync(0xFFFFFFFFu, s, o);
    const float dot = __shfl_sync(0xFFFFFFFFu, dot_l, lane_owner);

    if (lane == 0) {
        const float cosv = dot / fmaxf(sqrtf(s), 1e-8f);
        local += 1.0 - (double)cosv;
    }
}

__global__ __launch_bounds__(THREADS)
void cosine_loss_kernel(const float* __restrict__ logits,
                        const int* __restrict__ labels,
                        int N, int C, float* __restrict__ out, double inv_n) {
    const int lane  = threadIdx.x & 31;
    const int warp_in_block = threadIdx.x >> 5;
    const int gwarp = blockIdx.x * (THREADS >> 5) + warp_in_block;
    const int W = WARPS_TOTAL;

    double local = 0.0;

    RowBuf A, B, Cb;
    int r = gwarp;

    // Prologue: two rows in flight before the first consume.
    if (r < N)         load_row(A, logits, labels, r,     C, lane);
    if (r + W < N)     load_row(B, logits, labels, r + W, C, lane);

    // Each pass: issue-for-distance-2, then consume-the-oldest. 3 rows/pass.
    while (r < N) {
        if (r + 2 * W < N) load_row(Cb, logits, labels, r + 2 * W, C, lane);
        consume_row(A, lane, local);                       // row r

        if (r + W < N) {
            if (r + 3 * W < N) load_row(A, logits, labels, r + 3 * W, C, lane);
            consume_row(B, lane, local);                   // row r+W
        }
        if (r + 2 * W < N) {
            if (r + 4 * W < N) load_row(B, logits, labels, r + 4 * W, C, lane);
            consume_row(Cb, lane, local);                  // row r+2W
        }
        r += 3 * W;
    }

    // Block reduction, once per block.
    __shared__ double sh[THREADS >> 5];
    if (lane == 0) sh[warp_in_block] = local;
    __syncthreads();

    if (threadIdx.x == 0) {
        double t = 0.0;
        #pragma unroll
        for (int i = 0; i < (THREADS >> 5); i++) t += sh[i];
        atomicAdd(&g_state.acc, t);

        __threadfence();
        unsigned long long ticket = atomicAdd(&g_state.count, 1ULL);
        if (ticket == (unsigned long long)gridDim.x - 1ULL) {
            double acc = *(volatile double*)&g_state.acc;
            *out = (float)(acc * inv_n);
        }
    }
}

extern "C" void kernel_launch(void* const* d_in, const int* in_sizes, int n_in,
                              void* d_out, int out_size) {
    const float* logits = (const float*)d_in[0];
    const int*   labels = (const int*)d_in[1];
    float* out = (float*)d_out;

    const int N = in_sizes[1];          // rows == labels
    const int C = in_sizes[0] / N;      // 1000

    void* state_ptr = nullptr;
    cudaGetSymbolAddress(&state_ptr, g_state);
    cudaMemsetAsync(state_ptr, 0, sizeof(State), 0);

    cosine_loss_kernel<<<BLOCKS, THREADS>>>(logits, labels, N, C, out,
                                            1.0 / (double)N);
}